// round 15
// baseline (speedup 1.0000x reference)
#include <cuda_runtime.h>
#include <cuda_bf16.h>
#include <math.h>
#include <stdint.h>

#define C 256
#define ROWS 131072
#define EPS 0.001f
#define TOTCH 4096           // total K-chunks of 32 rows
#define NBH 96               // split-K blocks per half pair (p=0,2)
#define NBF 104              // split-K blocks for full pair (p=1)
#define NBT (NBH + NBF + NBH)   // 296 = one full wave at 2 blocks/SM
#define WH_NCH 8             // whiten k-chunks (256/32)

// ---------------- scratch ----------------
__device__ float g_psum[NBH * C];
__device__ float g_pG2[(size_t)NBT * 128 * 128];
__device__ float g_G[C * C];
__device__ float g_Lp[C * (C + 1) / 2];
__device__ float g_mean[C];
__device__ float g_Dinv[8 * 32 * 32];
__device__ float g_W[C * C];
__device__ float g_bias[C];
__device__ __nv_bfloat16 g_Whi[C * C];
__device__ __nv_bfloat16 g_Wlo[C * C];

__constant__ int c2_pi[3] = {0, 0, 1};
__constant__ int c2_pj[3] = {0, 1, 1};
__constant__ int c_off[3] = {0, NBH, NBH + NBF};
__constant__ int c_cnt[3] = {NBH, NBF, NBH};

// ---------------- helpers ----------------
__device__ __forceinline__ uint32_t smem_u32(const void* p) {
    uint32_t a;
    asm("{ .reg .u64 t; cvta.to.shared.u64 t, %1; cvt.u32.u64 %0, t; }" : "=r"(a) : "l"(p));
    return a;
}
__device__ __forceinline__ void cp16(uint32_t dst, const void* src) {
    asm volatile("cp.async.cg.shared.global [%0], [%1], 16;" :: "r"(dst), "l"(src));
}
#define CP_COMMIT() asm volatile("cp.async.commit_group;" ::: "memory")
#define CP_WAIT1()  asm volatile("cp.async.wait_group 1;" ::: "memory")
#define CP_WAIT0()  asm volatile("cp.async.wait_group 0;" ::: "memory")

__device__ __forceinline__ void mma_bf16(float* d, const uint32_t* a, const uint32_t* b) {
    asm volatile(
        "mma.sync.aligned.m16n8k16.row.col.f32.bf16.bf16.f32 "
        "{%0,%1,%2,%3}, {%4,%5,%6,%7}, {%8,%9}, {%0,%1,%2,%3};\n"
        : "+f"(d[0]), "+f"(d[1]), "+f"(d[2]), "+f"(d[3])
        : "r"(a[0]), "r"(a[1]), "r"(a[2]), "r"(a[3]), "r"(b[0]), "r"(b[1]));
}
__device__ __forceinline__ void ldsm4(uint32_t& d0, uint32_t& d1, uint32_t& d2, uint32_t& d3,
                                      uint32_t a) {
    asm volatile("ldmatrix.sync.aligned.m8n8.x4.shared.b16 {%0,%1,%2,%3}, [%4];"
                 : "=r"(d0), "=r"(d1), "=r"(d2), "=r"(d3) : "r"(a));
}
__device__ __forceinline__ void ldsm4t(uint32_t& d0, uint32_t& d1, uint32_t& d2, uint32_t& d3,
                                       uint32_t a) {
    asm volatile("ldmatrix.sync.aligned.m8n8.x4.trans.shared.b16 {%0,%1,%2,%3}, [%4];"
                 : "=r"(d0), "=r"(d1), "=r"(d2), "=r"(d3) : "r"(a));
}
__device__ __forceinline__ uint32_t pack2(__nv_bfloat16 lo, __nv_bfloat16 hi) {
    return (uint32_t)__bfloat16_as_ushort(lo) | ((uint32_t)__bfloat16_as_ushort(hi) << 16);
}
__device__ __forceinline__ uint32_t sw16(int row, int pp) {
    return ((uint32_t)(((row << 1) | pp) ^ ((row >> 2) & 1))) << 4;
}
__device__ __forceinline__ void split8(const float* f, uint4& H, uint4& L) {
    __nv_bfloat16 h[8], l[8];
#pragma unroll
    for (int e = 0; e < 8; ++e) {
        h[e] = __float2bfloat16_rn(f[e]);
        l[e] = __float2bfloat16_rn(f[e] - __bfloat162float(h[e]));
    }
    H = make_uint4(pack2(h[0], h[1]), pack2(h[2], h[3]), pack2(h[4], h[5]), pack2(h[6], h[7]));
    L = make_uint4(pack2(l[0], l[1]), pack2(l[2], l[3]), pack2(l[4], l[5]), pack2(l[6], l[7]));
}

// ---------------- 1) SYRK v2: row-major bf16 planes + ldmatrix.trans ----------------
// smem: planeH @0, planeL @16384 (full: rows of 512B = 256ch; half: rows of 256B = 128ch)
//       + csum scratch @ 16384 (halves overlay it past their 8KB planes: planeL @8192, sacc @16384)
__global__ __launch_bounds__(256, 2) void syrk_fused(const float* __restrict__ x) {
    extern __shared__ char smem[];
    uint32_t sb = smem_u32(smem);

    int tid = threadIdx.x, lane = tid & 31, warp = tid >> 5;
    int wm = warp >> 2, wn = warp & 3;
    int g4 = lane >> 2, t4 = lane & 3;

    int bid = blockIdx.x;
    int p, idx;
    if (bid < NBH)            { p = 0; idx = bid; }
    else if (bid < NBH + NBF) { p = 1; idx = bid - NBH; }
    else                      { p = 2; idx = bid - NBH - NBF; }
    int nb = (p == 1) ? NBF : NBH;
    int cs = (int)(((long long)idx * TOTCH) / nb);
    int ce = (int)(((long long)(idx + 1) * TOTCH) / nb);
    int nch = ce - cs;

    bool full = (p == 1);
    int chOff = full ? 0 : c2_pi[p] * 128;       // channel base this block reads
    uint32_t ROWB = full ? 512u : 256u;
    uint32_t plH = sb;
    uint32_t plL = sb + (full ? 16384u : 8192u);
    int aCp = 0;
    int bCp = full ? 16 : 0;
    size_t k0base = (size_t)cs * 32;

    float acc[4][4][4];
#pragma unroll
    for (int a = 0; a < 4; ++a)
#pragma unroll
        for (int b = 0; b < 4; ++b)
#pragma unroll
            for (int r = 0; r < 4; ++r) acc[a][b][r] = 0.f;

    // loader mapping
    // full:  cg8 = tid&31 (piece), kq = tid>>5 (krow group of 4)
    // half:  cg8 = tid&15 (piece), kq = tid>>4 (krow group of 2)
    int cg8 = full ? (tid & 31) : (tid & 15);
    int kq  = full ? (tid >> 5) : (tid >> 4);
    int KRT = full ? 4 : 2;                       // krows per thread
    float cssum[8];
#pragma unroll
    for (int e = 0; e < 8; ++e) cssum[e] = 0.f;

    float4 pf[8];
    auto loadpf = [&](int cc) {
        size_t k0 = k0base + (size_t)cc * 32;
#pragma unroll
        for (int r = 0; r < 4; ++r) {
            if (r >= KRT) break;
            size_t row = k0 + (size_t)(kq * KRT + r);
            const float* src = x + row * C + chOff + cg8 * 8;
            pf[r * 2 + 0] = *(const float4*)(src);
            pf[r * 2 + 1] = *(const float4*)(src + 4);
        }
    };

    // fragment address: lane -> krow' and piece select
    int krl0 = (lane & 7) + 8 * (lane >> 4);
    int psel = (lane >> 3) & 1;

    loadpf(0);
    for (int c = 0; c < nch; ++c) {
        __syncthreads();      // MMA(c-1) done reading planes
        // STS: split pf -> planes
#pragma unroll
        for (int r = 0; r < 4; ++r) {
            if (r >= KRT) break;
            int krow = kq * KRT + r;
            float f[8] = {pf[r*2].x, pf[r*2].y, pf[r*2].z, pf[r*2].w,
                          pf[r*2+1].x, pf[r*2+1].y, pf[r*2+1].z, pf[r*2+1].w};
            if (!full) {
#pragma unroll
                for (int e = 0; e < 8; ++e) cssum[e] += f[e];
            }
            uint4 H, L;
            split8(f, H, L);
            uint32_t off = (uint32_t)krow * ROWB + (uint32_t)((cg8 ^ (krow & 7)) << 4);
            *(uint4*)(smem + (plH - sb) + off) = H;
            *(uint4*)(smem + (plL - sb) + off) = L;
        }
        if (c + 1 < nch) loadpf(c + 1);   // LDG overlaps sync + MMA
        __syncthreads();      // planes visible

#pragma unroll
        for (int ks = 0; ks < 2; ++ks) {
            int krl = krl0 + ks * 16;
            uint32_t rb = (uint32_t)krl * ROWB;
            uint32_t xr = (uint32_t)((krl & 7) << 4);
            uint32_t bh[4][2], bl[4][2];
#pragma unroll
            for (int np = 0; np < 2; ++np) {
                uint32_t cp = (uint32_t)((bCp + wn * 4 + np * 2 + psel) << 4) ^ xr;
                ldsm4t(bh[np * 2][0], bh[np * 2 + 1][0], bh[np * 2][1], bh[np * 2 + 1][1],
                       plH + rb + cp);
                ldsm4t(bl[np * 2][0], bl[np * 2 + 1][0], bl[np * 2][1], bl[np * 2 + 1][1],
                       plL + rb + cp);
            }
#pragma unroll
            for (int mf = 0; mf < 4; ++mf) {
                uint32_t cp = (uint32_t)((aCp + wm * 8 + mf * 2 + psel) << 4) ^ xr;
                uint32_t ah[4], al[4];
                ldsm4t(ah[0], ah[1], ah[2], ah[3], plH + rb + cp);
                ldsm4t(al[0], al[1], al[2], al[3], plL + rb + cp);
#pragma unroll
                for (int nf = 0; nf < 4; ++nf) {
                    mma_bf16(acc[mf][nf], ah, bh[nf]);
                    mma_bf16(acc[mf][nf], ah, bl[nf]);
                    mma_bf16(acc[mf][nf], al, bh[nf]);
                }
            }
        }
    }

    // channel sums (half pairs only): reduce 16 krow-groups via smem
    if (!full) {
        float* sacc = (float*)(smem + 16384);
        __syncthreads();
#pragma unroll
        for (int e = 0; e < 8; ++e) sacc[kq * 128 + cg8 * 8 + e] = cssum[e];
        __syncthreads();
        if (tid < 128) {
            float s = 0.f;
#pragma unroll
            for (int k = 0; k < 16; ++k) s += sacc[k * 128 + tid];
            g_psum[idx * C + chOff + tid] = s;
        }
    }

    float* dst = g_pG2 + (size_t)bid * 16384;
#pragma unroll
    for (int mf = 0; mf < 4; ++mf)
#pragma unroll
        for (int nf = 0; nf < 4; ++nf) {
            int r = wm * 64 + mf * 16 + g4;
            int cc = wn * 32 + nf * 8 + t4 * 2;
            dst[r * 128 + cc]           = acc[mf][nf][0];
            dst[r * 128 + cc + 1]       = acc[mf][nf][1];
            dst[(r + 8) * 128 + cc]     = acc[mf][nf][2];
            dst[(r + 8) * 128 + cc + 1] = acc[mf][nf][3];
        }
}

// ---------------- 2) deterministic reduction (per-p partial counts) ----------------
__global__ __launch_bounds__(256) void reduceG2_kernel() {
    int p = blockIdx.x;
    int e = blockIdx.y * 256 + threadIdx.x;
    int cnt = c_cnt[p];
    const float* src = g_pG2 + (size_t)c_off[p] * 16384 + e;
    float s = 0.f;
    for (int c = 0; c < cnt; ++c) s += src[(size_t)c * 16384];
    int a = e >> 7, b = e & 127;
    int gi = c2_pi[p] * 128 + a, gj = c2_pj[p] * 128 + b;
    g_G[gi * C + gj] = s;
    g_G[gj * C + gi] = s;
}

// ---------------- 3a) mean + blocked Cholesky factor -> g_Lp, g_mean, g_Dinv ----------------
extern "C" __global__ __launch_bounds__(256) void chol_factor(int rows) {
    extern __shared__ float Lp[];
    __shared__ float m[C];
    __shared__ float scrD[32 * 33];
    __shared__ float sdinv[32];
    int tid = threadIdx.x, lane = tid & 31, warp = tid >> 5;

    {
        float s = 0.f;
#pragma unroll 8
        for (int b = 0; b < NBH; ++b) s += g_psum[b * C + tid];
        m[tid] = s / (float)rows;
    }
    __syncthreads();

    const int TOT = C * (C + 1) / 2;
    float scale = (1.f - EPS) / (float)(rows - 1);
    for (int idx = tid; idx < TOT; idx += 256) {
        int i = (int)((sqrtf(8.f * (float)idx + 1.f) - 1.f) * 0.5f);
        while ((i + 1) * (i + 2) / 2 <= idx) ++i;
        while (i * (i + 1) / 2 > idx) --i;
        int j = idx - i * (i + 1) / 2;
        float v = (g_G[i * C + j] - (float)rows * m[i] * m[j]) * scale;
        if (i == j) v += EPS;
        Lp[idx] = v;
    }
    __syncthreads();

    for (int pb = 0; pb < 8; ++pb) {
        int base = pb * 32;
        for (int idx = tid; idx < 1024; idx += 256) {
            int i = idx >> 5, j = idx & 31;
            int gi = base + i;
            scrD[i * 33 + j] = (j <= i) ? Lp[gi * (gi + 1) / 2 + base + j] : 0.f;
        }
        __syncthreads();
        if (warp == 0) {
            for (int k = 0; k < 32; ++k) {
                if (lane == 0) scrD[k * 33 + k] = sqrtf(scrD[k * 33 + k]);
                __syncwarp();
                float inv = 1.f / scrD[k * 33 + k];
                if (lane > k) scrD[lane * 33 + k] *= inv;
                __syncwarp();
                if (lane > k) {
                    float lik = scrD[lane * 33 + k];
                    for (int j = k + 1; j <= lane; ++j)
                        scrD[lane * 33 + j] -= lik * scrD[j * 33 + k];
                }
                __syncwarp();
            }
        }
        __syncthreads();
        if (tid < 32) sdinv[tid] = 1.f / scrD[tid * 33 + tid];
        for (int idx = tid; idx < 1024; idx += 256) {
            int i = idx >> 5, j = idx & 31;
            if (j <= i) {
                int gi = base + i;
                Lp[gi * (gi + 1) / 2 + base + j] = scrD[i * 33 + j];
            }
        }
        __syncthreads();
        int R = 256 - base - 32;
        if (tid < R) {
            int gi = base + 32 + tid;
            int ro = gi * (gi + 1) / 2 + base;
            float r[32];
#pragma unroll
            for (int t = 0; t < 32; ++t) r[t] = Lp[ro + t];
#pragma unroll
            for (int k = 0; k < 32; ++k) {
                float s = r[k];
                for (int t = 0; t < k; ++t) s -= r[t] * scrD[k * 33 + t];
                r[k] = s * sdinv[k];
            }
#pragma unroll
            for (int t = 0; t < 32; ++t) Lp[ro + t] = r[t];
        }
        __syncthreads();
        if (R > 0) {
            int w = warp;
            for (int rt = 0; rt * 128 < R; ++rt) {
                int gbase = base + 32 + rt * 128;
                int tmax = min(255, gbase + 127);
                int gi[4]; bool act[4];
                float pi[4][32];
#pragma unroll
                for (int q = 0; q < 4; ++q) {
                    gi[q] = gbase + q * 32 + lane;
                    act[q] = gi[q] < 256;
                    if (act[q]) {
                        int ro = gi[q] * (gi[q] + 1) / 2 + base;
#pragma unroll
                        for (int t = 0; t < 32; ++t) pi[q][t] = Lp[ro + t];
                    }
                }
                for (int jt = base + 32; jt <= tmax; jt += 32) {
                    int j0 = jt + w * 4;
                    if (j0 > tmax) continue;
                    int rj0 = j0 * (j0 + 1) / 2 + base;
                    int rj1 = (j0 + 1) * (j0 + 2) / 2 + base;
                    int rj2 = (j0 + 2) * (j0 + 3) / 2 + base;
                    int rj3 = (j0 + 3) * (j0 + 4) / 2 + base;
                    float a[4][4];
#pragma unroll
                    for (int q = 0; q < 4; ++q)
#pragma unroll
                        for (int e = 0; e < 4; ++e) a[q][e] = 0.f;
#pragma unroll
                    for (int k = 0; k < 32; ++k) {
                        float pj0 = Lp[rj0 + k];
                        float pj1 = Lp[rj1 + k];
                        float pj2 = Lp[rj2 + k];
                        float pj3 = Lp[rj3 + k];
#pragma unroll
                        for (int q = 0; q < 4; ++q) {
                            float pv = pi[q][k];
                            a[q][0] += pv * pj0;
                            a[q][1] += pv * pj1;
                            a[q][2] += pv * pj2;
                            a[q][3] += pv * pj3;
                        }
                    }
#pragma unroll
                    for (int q = 0; q < 4; ++q) {
                        if (!act[q]) continue;
                        int ro = gi[q] * (gi[q] + 1) / 2;
#pragma unroll
                        for (int e = 0; e < 4; ++e) {
                            int j = j0 + e;
                            if (j <= gi[q]) Lp[ro + j] -= a[q][e];
                        }
                    }
                }
            }
        }
        __syncthreads();
    }

    {
        int b = tid >> 5, j = tid & 31, rb = b * 32;
        float w[32];
#pragma unroll
        for (int i = 0; i < 32; ++i) {
            float s = (i == j) ? 1.f : 0.f;
            const float* lrow = &Lp[(rb + i) * (rb + i + 1) / 2 + rb];
#pragma unroll
            for (int k = 0; k < 32; ++k)
                if (k < i) s -= lrow[k] * w[k];
            w[i] = (i >= j) ? s / lrow[i] : 0.f;
        }
#pragma unroll
        for (int i = 0; i < 32; ++i) g_Dinv[b * 1024 + i * 32 + j] = w[i];
    }

    for (int idx = tid; idx < TOT; idx += 256) g_Lp[idx] = Lp[idx];
    if (tid < C) g_mean[tid] = m[tid];
}

// ---------------- 3b) panel TRSM via Dinv GEMMs ----------------
__global__ __launch_bounds__(256) void trsm_inv() {
    extern __shared__ float sh[];
    float* Lpack = sh;
    float* Wc = sh + 32896;
    __shared__ float Rt[32 * 33];
    __shared__ float Dv[32 * 33];
    int tid = threadIdx.x, lane = tid & 31, w = tid >> 5;
    int base = blockIdx.x * 32;
    int pb0 = blockIdx.x;
    int c0 = w * 4;

    for (int idx = tid; idx < C * (C + 1) / 2; idx += 256) Lpack[idx] = g_Lp[idx];
    __syncthreads();

    for (int rp = pb0; rp < 8; ++rp) {
        int rbase = rp * 32;
        float a0 = 0, a1 = 0, a2 = 0, a3 = 0;
        for (int pp = pb0; pp < rp; ++pp) {
            int kb = pp * 32;
            int ro = (rbase + lane) * (rbase + lane + 1) / 2 + kb;
#pragma unroll 8
            for (int k = 0; k < 32; ++k) {
                float lv = Lpack[ro + k];
                const float* wr = &Wc[(kb + k) * 33 + c0];
                a0 += lv * wr[0]; a1 += lv * wr[1]; a2 += lv * wr[2]; a3 += lv * wr[3];
            }
        }
        bool idp = (rp == pb0);
        Rt[lane * 33 + c0 + 0] = ((idp && lane == c0 + 0) ? 1.f : 0.f) - a0;
        Rt[lane * 33 + c0 + 1] = ((idp && lane == c0 + 1) ? 1.f : 0.f) - a1;
        Rt[lane * 33 + c0 + 2] = ((idp && lane == c0 + 2) ? 1.f : 0.f) - a2;
        Rt[lane * 33 + c0 + 3] = ((idp && lane == c0 + 3) ? 1.f : 0.f) - a3;
#pragma unroll
        for (int q = 0; q < 4; ++q) {
            int idx = tid + 256 * q;
            int r = idx >> 5, cc = idx & 31;
            Dv[r * 33 + cc] = g_Dinv[rp * 1024 + r * 32 + cc];
        }
        __syncthreads();
        float o0 = 0, o1 = 0, o2 = 0, o3 = 0;
#pragma unroll 8
        for (int k = 0; k < 32; ++k) {
            float dv = Dv[lane * 33 + k];
            const float* rr = &Rt[k * 33 + c0];
            o0 += dv * rr[0]; o1 += dv * rr[1]; o2 += dv * rr[2]; o3 += dv * rr[3];
        }
        Wc[(rbase + lane) * 33 + c0 + 0] = o0;
        Wc[(rbase + lane) * 33 + c0 + 1] = o1;
        Wc[(rbase + lane) * 33 + c0 + 2] = o2;
        Wc[(rbase + lane) * 33 + c0 + 3] = o3;
        __syncthreads();
    }

    for (int idx = tid; idx < 256 * 32; idx += 256) {
        int i = idx >> 5, c = idx & 31;
        g_W[i * C + base + c] = (i >= base) ? Wc[i * 33 + c] : 0.f;
    }
    for (int idx = tid; idx < 256 * 8; idx += 256) {
        int i = idx >> 3, cq = idx & 7;
        float f[4];
#pragma unroll
        for (int e = 0; e < 4; ++e)
            f[e] = (i >= base) ? Wc[i * 33 + cq * 4 + e] : 0.f;
        __nv_bfloat16 h[4], l[4];
#pragma unroll
        for (int e = 0; e < 4; ++e) {
            h[e] = __float2bfloat16_rn(f[e]);
            l[e] = __float2bfloat16_rn(f[e] - __bfloat162float(h[e]));
        }
        int off = i * C + base + cq * 4;
        *(uint2*)(g_Whi + off) = make_uint2(pack2(h[0], h[1]), pack2(h[2], h[3]));
        *(uint2*)(g_Wlo + off) = make_uint2(pack2(l[0], l[1]), pack2(l[2], l[3]));
    }
}

// ---------------- 3c) bias = W @ mean ----------------
__global__ __launch_bounds__(256) void bias_kernel() {
    int i = threadIdx.x;
    float s = 0.f;
#pragma unroll 4
    for (int j = 0; j <= i; ++j) s += g_W[i * C + j] * g_mean[j];
    g_bias[i] = s;
}

// ---------------- 4) whitening: triangular skip, SMSP-balanced (R13-proven) ----------------
// smem: X stages [2][16KB] @0; W stages [3][32KB] @32768.
__global__ __launch_bounds__(512, 1) void whiten_fused(const float* __restrict__ x,
                                                       float* __restrict__ out) {
    extern __shared__ char smem[];
    __shared__ float sbias[C];
    uint32_t sb = smem_u32(smem);

    int tid = threadIdx.x, lane = tid & 31, warp = tid >> 5;
    int wm = warp & 3, wn = warp >> 2;
    int g4 = lane >> 2, t4 = lane & 3;
    int lrow = lane & 15, lpp = lane >> 4;
    size_t m0 = (size_t)blockIdx.x * 128;
    int mylast = 2 * wn + 1;

    if (tid < C) sbias[tid] = g_bias[tid];

    float acc[2][8][4];
#pragma unroll
    for (int a = 0; a < 2; ++a)
#pragma unroll
        for (int b = 0; b < 8; ++b)
#pragma unroll
            for (int r = 0; r < 4; ++r) acc[a][b][r] = 0.f;

    int xrow = tid >> 2, xpp = tid & 3;
    const float* xp = x + (m0 + xrow) * C + xpp * 8;

    auto issueW = [&](int cc, int st) {
        int k0 = cc * 32;
#pragma unroll
        for (int q = 0; q < 4; ++q) {
            int idx = tid + 512 * q;
            int plm = idx >> 10, rem = idx & 1023;
            int n = rem >> 2, sl = (rem >> 1) & 1, pp = rem & 1;
            const __nv_bfloat16* plane = plm ? g_Wlo : g_Whi;
            cp16(sb + 32768u + (uint32_t)st * 32768 + (uint32_t)plm * 16384 +
                     (uint32_t)sl * 8192 + sw16(n, pp),
                 plane + (size_t)n * C + k0 + sl * 16 + pp * 8);
        }
    };

    float4 xv0 = *(const float4*)(xp);
    float4 xv1 = *(const float4*)(xp + 4);
    issueW(0, 0); CP_COMMIT();

    for (int c = 0; c < WH_NCH; ++c) {
        int ps = c & 1;
        int st = c % 3;
        {
            float f[8] = {xv0.x, xv0.y, xv0.z, xv0.w, xv1.x, xv1.y, xv1.z, xv1.w};
            uint4 H, L;
            split8(f, H, L);
            uint32_t off = (uint32_t)ps * 16384 + (uint32_t)(xpp >> 1) * 4096 + sw16(xrow, xpp & 1);
            *(uint4*)(smem + off) = H;
            *(uint4*)(smem + 8192 + off) = L;
        }
        if (c + 1 < WH_NCH) {
            xv0 = *(const float4*)(xp + (c + 1) * 32);
            xv1 = *(const float4*)(xp + (c + 1) * 32 + 4);
            issueW(c + 1, (c + 1) % 3); CP_COMMIT(); CP_WAIT1();
        } else CP_WAIT0();
        __syncthreads();

        if (c <= mylast) {
#pragma unroll
            for (int ks = 0; ks < 2; ++ks) {
                uint32_t XH = sb + (uint32_t)ps * 16384 + (uint32_t)ks * 4096;
                uint32_t XL = XH + 8192;
                uint32_t WHb = sb + 32768u + (uint32_t)st * 32768 + (uint32_t)ks * 8192;
                uint32_t WLb = WHb + 16384;
                uint32_t bh[8][2], bl[8][2];
#pragma unroll
                for (int np = 0; np < 4; ++np) {
                    int nr = wn * 64 + np * 16 + lrow;
                    ldsm4(bh[np * 2][0], bh[np * 2 + 1][0], bh[np * 2][1], bh[np * 2 + 1][1],
                          WHb + sw16(nr, lpp));
                    ldsm4(bl[np * 2][0], bl[np * 2 + 1][0], bl[np * 2][1], bl[np * 2 + 1][1],
                          WLb + sw16(nr, lpp));
                }
#pragma unroll
                for (int mf = 0; mf < 2; ++mf) {
                    int mr = wm * 32 + mf * 16 + lrow;
                    uint32_t ah[4], al[4];
                    ldsm4(ah[0], ah[1], ah[2], ah[3], XH + sw16(mr, lpp));
                    ldsm4(al[0], al[1], al[2], al[3], XL + sw16(mr, lpp));
#pragma unroll
                    for (int nf = 0; nf < 8; ++nf) {
                        mma_bf16(acc[mf][nf], ah, bh[nf]);
                        mma_bf16(acc[mf][nf], ah, bl[nf]);
                        mma_bf16(acc[mf][nf], al, bh[nf]);
                    }
                }
            }
        }
    }

#pragma unroll
    for (int mf = 0; mf < 2; ++mf)
#pragma unroll
        for (int nf = 0; nf < 8; ++nf) {
            int r = wm * 32 + mf * 16 + g4;
            int cc = wn * 64 + nf * 8 + t4 * 2;
            float b0 = sbias[cc], b1 = sbias[cc + 1];
            *(float2*)&out[(m0 + r) * C + cc]     = make_float2(acc[mf][nf][0] - b0, acc[mf][nf][1] - b1);
            *(float2*)&out[(m0 + r + 8) * C + cc] = make_float2(acc[mf][nf][2] - b0, acc[mf][nf][3] - b1);
        }
}

// ---------------- launch ----------------
extern "C" void kernel_launch(void* const* d_in, const int* in_sizes, int n_in,
                              void* d_out, int out_size) {
    const float* x = (const float*)d_in[0];
    float* out = (float*)d_out;
    int rows = in_sizes[0] / C;          // 131072

    static const int syrk_smem = 40960;   // planes 32KB + csum scratch 8KB
    cudaFuncSetAttribute(syrk_fused, cudaFuncAttributeMaxDynamicSharedMemorySize, syrk_smem);
    syrk_fused<<<NBT, 256, syrk_smem>>>(x);

    reduceG2_kernel<<<dim3(3, 64), 256>>>();

    static const int chol_smem = (C * (C + 1) / 2) * (int)sizeof(float);  // 131584
    cudaFuncSetAttribute(chol_factor, cudaFuncAttributeMaxDynamicSharedMemorySize, chol_smem);
    chol_factor<<<1, 256, chol_smem>>>(rows);

    static const int trsm_smem = (C * (C + 1) / 2 + C * 33) * (int)sizeof(float);  // 165376
    cudaFuncSetAttribute(trsm_inv, cudaFuncAttributeMaxDynamicSharedMemorySize, trsm_smem);
    trsm_inv<<<8, 256, trsm_smem>>>();

    bias_kernel<<<1, 256>>>();

    static const int wh_smem = 131072;
    cudaFuncSetAttribute(whiten_fused, cudaFuncAttributeMaxDynamicSharedMemorySize, wh_smem);
    whiten_fused<<<rows / 128, 512, wh_smem>>>(x, out);
}

// round 16
// speedup vs baseline: 1.0901x; 1.0901x over previous
#include <cuda_runtime.h>
#include <cuda_bf16.h>
#include <math.h>
#include <stdint.h>

#define C 256
#define ROWS 131072
#define EPS 0.001f
#define TOTCH 4096           // total K-chunks of 32 rows
#define NBH 88               // split-K blocks per half pair (p=0,2)
#define NBF 120              // split-K blocks for full pair (p=1)
#define NBT (NBH + NBF + NBH)   // 296 = one full wave at 2 blocks/SM
#define WH_NCH 8             // whiten k-chunks (256/32)

// ---------------- scratch ----------------
__device__ float g_psum[NBF * C];
__device__ float g_pG2[(size_t)NBT * 128 * 128];
__device__ float g_G[C * C];
__device__ float g_Lp[C * (C + 1) / 2];
__device__ float g_mean[C];
__device__ float g_Dinv[8 * 32 * 32];
__device__ float g_W[C * C];
__device__ float g_bias[C];
__device__ __nv_bfloat16 g_Whi[C * C];
__device__ __nv_bfloat16 g_Wlo[C * C];

__constant__ int c2_pi[3] = {0, 0, 1};
__constant__ int c2_pj[3] = {0, 1, 1};
__constant__ int c_off[3] = {0, NBH, NBH + NBF};
__constant__ int c_cnt[3] = {NBH, NBF, NBH};

// ---------------- helpers ----------------
__device__ __forceinline__ uint32_t smem_u32(const void* p) {
    uint32_t a;
    asm("{ .reg .u64 t; cvta.to.shared.u64 t, %1; cvt.u32.u64 %0, t; }" : "=r"(a) : "l"(p));
    return a;
}
__device__ __forceinline__ void cp16(uint32_t dst, const void* src) {
    asm volatile("cp.async.cg.shared.global [%0], [%1], 16;" :: "r"(dst), "l"(src));
}
#define CP_COMMIT() asm volatile("cp.async.commit_group;" ::: "memory")
#define CP_WAIT1()  asm volatile("cp.async.wait_group 1;" ::: "memory")
#define CP_WAIT0()  asm volatile("cp.async.wait_group 0;" ::: "memory")

__device__ __forceinline__ void mma_bf16(float* d, const uint32_t* a, const uint32_t* b) {
    asm volatile(
        "mma.sync.aligned.m16n8k16.row.col.f32.bf16.bf16.f32 "
        "{%0,%1,%2,%3}, {%4,%5,%6,%7}, {%8,%9}, {%0,%1,%2,%3};\n"
        : "+f"(d[0]), "+f"(d[1]), "+f"(d[2]), "+f"(d[3])
        : "r"(a[0]), "r"(a[1]), "r"(a[2]), "r"(a[3]), "r"(b[0]), "r"(b[1]));
}
__device__ __forceinline__ void ldsm4(uint32_t& d0, uint32_t& d1, uint32_t& d2, uint32_t& d3,
                                      uint32_t a) {
    asm volatile("ldmatrix.sync.aligned.m8n8.x4.shared.b16 {%0,%1,%2,%3}, [%4];"
                 : "=r"(d0), "=r"(d1), "=r"(d2), "=r"(d3) : "r"(a));
}
__device__ __forceinline__ uint32_t pack2(__nv_bfloat16 lo, __nv_bfloat16 hi) {
    return (uint32_t)__bfloat16_as_ushort(lo) | ((uint32_t)__bfloat16_as_ushort(hi) << 16);
}
__device__ __forceinline__ uint32_t sw16(int row, int pp) {
    return ((uint32_t)(((row << 1) | pp) ^ ((row >> 2) & 1))) << 4;
}
__device__ __forceinline__ void split8(const float* f, uint4& H, uint4& L) {
    __nv_bfloat16 h[8], l[8];
#pragma unroll
    for (int e = 0; e < 8; ++e) {
        h[e] = __float2bfloat16_rn(f[e]);
        l[e] = __float2bfloat16_rn(f[e] - __bfloat162float(h[e]));
    }
    H = make_uint4(pack2(h[0], h[1]), pack2(h[2], h[3]), pack2(h[4], h[5]), pack2(h[6], h[7]));
    L = make_uint4(pack2(l[0], l[1]), pack2(l[2], l[3]), pack2(l[4], l[5]), pack2(l[6], l[7]));
}

// ---------------- 1) SYRK fused: one-wave, work-balanced split-K (R14-proven) ----------------
// smem bytes: fp32 stages [2][32KB] @0; planes @65536: AH,AL,BH,BL 8KB each.
__global__ __launch_bounds__(256, 2) void syrk_fused(const float* __restrict__ x) {
    extern __shared__ char smem[];
    uint32_t sb = smem_u32(smem);
    uint32_t pl = sb + 65536;
    const float* sf = (const float*)smem;

    int tid = threadIdx.x, lane = tid & 31, warp = tid >> 5;
    int wm = warp >> 2, wn = warp & 3;
    int g4 = lane >> 2, t4 = lane & 3;
    int lrow = lane & 15, lpp = lane >> 4;

    int bid = blockIdx.x;
    int p, idx;
    if (bid < NBH)            { p = 0; idx = bid; }
    else if (bid < NBH + NBF) { p = 1; idx = bid - NBH; }
    else                      { p = 2; idx = bid - NBH - NBF; }
    int nb = (p == 1) ? NBF : NBH;
    int cs = (int)(((long long)idx * TOTCH) / nb);
    int ce = (int)(((long long)(idx + 1) * TOTCH) / nb);
    int nch = ce - cs;

    int ti = c2_pi[p];
    bool full = (p == 1);
    size_t k0base = (size_t)cs * 32;
    uint32_t bBase = pl + (full ? 16384u : 0u);

    float acc[4][4][4];
#pragma unroll
    for (int a = 0; a < 4; ++a)
#pragma unroll
        for (int b = 0; b < 4; ++b)
#pragma unroll
            for (int r = 0; r < 4; ++r) acc[a][b][r] = 0.f;
    float csum = 0.f;

    auto issue = [&](int cc, int s) {
        size_t k0 = k0base + (size_t)cc * 32;
        if (full) {
#pragma unroll
            for (int q = 0; q < 8; ++q) {
                int i2 = tid + 256 * q;
                int row = i2 >> 6, pc = i2 & 63;
                cp16(sb + (uint32_t)s * 32768 + (uint32_t)row * 1024 + (uint32_t)pc * 16,
                     x + (k0 + row) * C + pc * 4);
            }
        } else {
#pragma unroll
            for (int q = 0; q < 4; ++q) {
                int i2 = tid + 256 * q;
                int row = i2 >> 5, pc = i2 & 31;
                cp16(sb + (uint32_t)s * 32768 + (uint32_t)row * 512 + (uint32_t)pc * 16,
                     x + (k0 + row) * C + ti * 128 + pc * 4);
            }
        }
    };

    issue(0, 0); CP_COMMIT();
    for (int c = 0; c < nch; ++c) {
        int s = c & 1;
        if (c + 1 < nch) { issue(c + 1, s ^ 1); CP_COMMIT(); CP_WAIT1(); }
        else CP_WAIT0();
        __syncthreads();

        if (full) {
            int ch = tid;
            uint32_t stg = (uint32_t)s * 8192;
            uint32_t boff = 65536u + (uint32_t)(ch >> 7) * 16384;
            int chl = ch & 127;
#pragma unroll
            for (int kp = 0; kp < 4; ++kp) {
                float f[8];
#pragma unroll
                for (int e = 0; e < 8; ++e) {
                    f[e] = sf[stg + (uint32_t)(kp * 8 + e) * 256 + ch];
                    csum += f[e];
                }
                uint4 H, L;
                split8(f, H, L);
                uint32_t off = (uint32_t)(kp >> 1) * 4096 + sw16(chl, kp & 1);
                *(uint4*)(smem + boff + off) = H;
                *(uint4*)(smem + boff + 8192 + off) = L;
            }
        } else {
            int ch = tid & 127, kb = tid >> 7;
            uint32_t stg = (uint32_t)s * 8192;
#pragma unroll
            for (int q = 0; q < 2; ++q) {
                int kp = kb * 2 + q;
                float f[8];
#pragma unroll
                for (int e = 0; e < 8; ++e)
                    f[e] = sf[stg + (uint32_t)(kp * 8 + e) * 128 + ch];
                uint4 H, L;
                split8(f, H, L);
                uint32_t off = (uint32_t)(kp >> 1) * 4096 + sw16(ch, kp & 1);
                *(uint4*)(smem + 65536 + off) = H;
                *(uint4*)(smem + 65536 + 8192 + off) = L;
            }
        }
        __syncthreads();

#pragma unroll
        for (int ks = 0; ks < 2; ++ks) {
            uint32_t AH = pl + (uint32_t)ks * 4096;
            uint32_t AL = AH + 8192;
            uint32_t BH = bBase + (uint32_t)ks * 4096;
            uint32_t BL = BH + 8192;
            uint32_t bh[4][2], bl[4][2];
#pragma unroll
            for (int np = 0; np < 2; ++np) {
                int nr = wn * 32 + np * 16 + lrow;
                ldsm4(bh[np * 2][0], bh[np * 2 + 1][0], bh[np * 2][1], bh[np * 2 + 1][1],
                      BH + sw16(nr, lpp));
                ldsm4(bl[np * 2][0], bl[np * 2 + 1][0], bl[np * 2][1], bl[np * 2 + 1][1],
                      BL + sw16(nr, lpp));
            }
#pragma unroll
            for (int mf = 0; mf < 4; ++mf) {
                int mr = wm * 64 + mf * 16 + lrow;
                uint32_t ah[4], al[4];
                ldsm4(ah[0], ah[1], ah[2], ah[3], AH + sw16(mr, lpp));
                ldsm4(al[0], al[1], al[2], al[3], AL + sw16(mr, lpp));
#pragma unroll
                for (int nf = 0; nf < 4; ++nf) {
                    mma_bf16(acc[mf][nf], ah, bh[nf]);
                    mma_bf16(acc[mf][nf], ah, bl[nf]);
                    mma_bf16(acc[mf][nf], al, bh[nf]);
                }
            }
        }
    }

    if (full) g_psum[idx * C + tid] = csum;

    float* dst = g_pG2 + (size_t)bid * 16384;
#pragma unroll
    for (int mf = 0; mf < 4; ++mf)
#pragma unroll
        for (int nf = 0; nf < 4; ++nf) {
            int r = wm * 64 + mf * 16 + g4;
            int cc = wn * 32 + nf * 8 + t4 * 2;
            dst[r * 128 + cc]           = acc[mf][nf][0];
            dst[r * 128 + cc + 1]       = acc[mf][nf][1];
            dst[(r + 8) * 128 + cc]     = acc[mf][nf][2];
            dst[(r + 8) * 128 + cc + 1] = acc[mf][nf][3];
        }
}

// ---------------- 2) deterministic reduction: 4 independent accumulator chains ----------------
__global__ __launch_bounds__(256) void reduceG2_kernel() {
    int p = blockIdx.x;
    int e = blockIdx.y * 256 + threadIdx.x;
    int cnt = c_cnt[p];
    const float* src = g_pG2 + (size_t)c_off[p] * 16384 + e;
    float s0 = 0.f, s1 = 0.f, s2 = 0.f, s3 = 0.f;
    int c = 0;
    for (; c + 4 <= cnt; c += 4) {
        s0 += src[(size_t)(c + 0) * 16384];
        s1 += src[(size_t)(c + 1) * 16384];
        s2 += src[(size_t)(c + 2) * 16384];
        s3 += src[(size_t)(c + 3) * 16384];
    }
    for (; c < cnt; ++c) s0 += src[(size_t)c * 16384];
    float s = (s0 + s1) + (s2 + s3);
    int a = e >> 7, b = e & 127;
    int gi = c2_pi[p] * 128 + a, gj = c2_pj[p] * 128 + b;
    g_G[gi * C + gj] = s;
    g_G[gj * C + gi] = s;
}

// ---------------- 3a) mean + blocked Cholesky factor -> g_Lp, g_mean, g_Dinv ----------------
extern "C" __global__ __launch_bounds__(256) void chol_factor(int rows) {
    extern __shared__ float Lp[];
    __shared__ float m[C];
    __shared__ float scrD[32 * 33];
    __shared__ float sdinv[32];
    int tid = threadIdx.x, lane = tid & 31, warp = tid >> 5;

    {
        float s = 0.f;
#pragma unroll 8
        for (int b = 0; b < NBF; ++b) s += g_psum[b * C + tid];
        m[tid] = s / (float)rows;
    }
    __syncthreads();

    const int TOT = C * (C + 1) / 2;
    float scale = (1.f - EPS) / (float)(rows - 1);
    for (int idx = tid; idx < TOT; idx += 256) {
        int i = (int)((sqrtf(8.f * (float)idx + 1.f) - 1.f) * 0.5f);
        while ((i + 1) * (i + 2) / 2 <= idx) ++i;
        while (i * (i + 1) / 2 > idx) --i;
        int j = idx - i * (i + 1) / 2;
        float v = (g_G[i * C + j] - (float)rows * m[i] * m[j]) * scale;
        if (i == j) v += EPS;
        Lp[idx] = v;
    }
    __syncthreads();

    for (int pb = 0; pb < 8; ++pb) {
        int base = pb * 32;
        for (int idx = tid; idx < 1024; idx += 256) {
            int i = idx >> 5, j = idx & 31;
            int gi = base + i;
            scrD[i * 33 + j] = (j <= i) ? Lp[gi * (gi + 1) / 2 + base + j] : 0.f;
        }
        __syncthreads();
        if (warp == 0) {
            for (int k = 0; k < 32; ++k) {
                if (lane == 0) scrD[k * 33 + k] = sqrtf(scrD[k * 33 + k]);
                __syncwarp();
                float inv = 1.f / scrD[k * 33 + k];
                if (lane > k) scrD[lane * 33 + k] *= inv;
                __syncwarp();
                if (lane > k) {
                    float lik = scrD[lane * 33 + k];
                    for (int j = k + 1; j <= lane; ++j)
                        scrD[lane * 33 + j] -= lik * scrD[j * 33 + k];
                }
                __syncwarp();
            }
        }
        __syncthreads();
        if (tid < 32) sdinv[tid] = 1.f / scrD[tid * 33 + tid];
        for (int idx = tid; idx < 1024; idx += 256) {
            int i = idx >> 5, j = idx & 31;
            if (j <= i) {
                int gi = base + i;
                Lp[gi * (gi + 1) / 2 + base + j] = scrD[i * 33 + j];
            }
        }
        __syncthreads();
        int R = 256 - base - 32;
        if (tid < R) {
            int gi = base + 32 + tid;
            int ro = gi * (gi + 1) / 2 + base;
            float r[32];
#pragma unroll
            for (int t = 0; t < 32; ++t) r[t] = Lp[ro + t];
#pragma unroll
            for (int k = 0; k < 32; ++k) {
                float s = r[k];
                for (int t = 0; t < k; ++t) s -= r[t] * scrD[k * 33 + t];
                r[k] = s * sdinv[k];
            }
#pragma unroll
            for (int t = 0; t < 32; ++t) Lp[ro + t] = r[t];
        }
        __syncthreads();
        if (R > 0) {
            int w = warp;
            for (int rt = 0; rt * 128 < R; ++rt) {
                int gbase = base + 32 + rt * 128;
                int tmax = min(255, gbase + 127);
                int gi[4]; bool act[4];
                float pi[4][32];
#pragma unroll
                for (int q = 0; q < 4; ++q) {
                    gi[q] = gbase + q * 32 + lane;
                    act[q] = gi[q] < 256;
                    if (act[q]) {
                        int ro = gi[q] * (gi[q] + 1) / 2 + base;
#pragma unroll
                        for (int t = 0; t < 32; ++t) pi[q][t] = Lp[ro + t];
                    }
                }
                for (int jt = base + 32; jt <= tmax; jt += 32) {
                    int j0 = jt + w * 4;
                    if (j0 > tmax) continue;
                    int rj0 = j0 * (j0 + 1) / 2 + base;
                    int rj1 = (j0 + 1) * (j0 + 2) / 2 + base;
                    int rj2 = (j0 + 2) * (j0 + 3) / 2 + base;
                    int rj3 = (j0 + 3) * (j0 + 4) / 2 + base;
                    float a[4][4];
#pragma unroll
                    for (int q = 0; q < 4; ++q)
#pragma unroll
                        for (int e = 0; e < 4; ++e) a[q][e] = 0.f;
#pragma unroll
                    for (int k = 0; k < 32; ++k) {
                        float pj0 = Lp[rj0 + k];
                        float pj1 = Lp[rj1 + k];
                        float pj2 = Lp[rj2 + k];
                        float pj3 = Lp[rj3 + k];
#pragma unroll
                        for (int q = 0; q < 4; ++q) {
                            float pv = pi[q][k];
                            a[q][0] += pv * pj0;
                            a[q][1] += pv * pj1;
                            a[q][2] += pv * pj2;
                            a[q][3] += pv * pj3;
                        }
                    }
#pragma unroll
                    for (int q = 0; q < 4; ++q) {
                        if (!act[q]) continue;
                        int ro = gi[q] * (gi[q] + 1) / 2;
#pragma unroll
                        for (int e = 0; e < 4; ++e) {
                            int j = j0 + e;
                            if (j <= gi[q]) Lp[ro + j] -= a[q][e];
                        }
                    }
                }
            }
        }
        __syncthreads();
    }

    {
        int b = tid >> 5, j = tid & 31, rb = b * 32;
        float w[32];
#pragma unroll
        for (int i = 0; i < 32; ++i) {
            float s = (i == j) ? 1.f : 0.f;
            const float* lrow = &Lp[(rb + i) * (rb + i + 1) / 2 + rb];
#pragma unroll
            for (int k = 0; k < 32; ++k)
                if (k < i) s -= lrow[k] * w[k];
            w[i] = (i >= j) ? s / lrow[i] : 0.f;
        }
#pragma unroll
        for (int i = 0; i < 32; ++i) g_Dinv[b * 1024 + i * 32 + j] = w[i];
    }

    for (int idx = tid; idx < TOT; idx += 256) g_Lp[idx] = Lp[idx];
    if (tid < C) g_mean[tid] = m[tid];
}

// ---------------- 3b) panel TRSM via Dinv GEMMs ----------------
__global__ __launch_bounds__(256) void trsm_inv() {
    extern __shared__ float sh[];
    float* Lpack = sh;
    float* Wc = sh + 32896;
    __shared__ float Rt[32 * 33];
    __shared__ float Dv[32 * 33];
    int tid = threadIdx.x, lane = tid & 31, w = tid >> 5;
    int base = blockIdx.x * 32;
    int pb0 = blockIdx.x;
    int c0 = w * 4;

    for (int idx = tid; idx < C * (C + 1) / 2; idx += 256) Lpack[idx] = g_Lp[idx];
    __syncthreads();

    for (int rp = pb0; rp < 8; ++rp) {
        int rbase = rp * 32;
        float a0 = 0, a1 = 0, a2 = 0, a3 = 0;
        for (int pp = pb0; pp < rp; ++pp) {
            int kb = pp * 32;
            int ro = (rbase + lane) * (rbase + lane + 1) / 2 + kb;
#pragma unroll 8
            for (int k = 0; k < 32; ++k) {
                float lv = Lpack[ro + k];
                const float* wr = &Wc[(kb + k) * 33 + c0];
                a0 += lv * wr[0]; a1 += lv * wr[1]; a2 += lv * wr[2]; a3 += lv * wr[3];
            }
        }
        bool idp = (rp == pb0);
        Rt[lane * 33 + c0 + 0] = ((idp && lane == c0 + 0) ? 1.f : 0.f) - a0;
        Rt[lane * 33 + c0 + 1] = ((idp && lane == c0 + 1) ? 1.f : 0.f) - a1;
        Rt[lane * 33 + c0 + 2] = ((idp && lane == c0 + 2) ? 1.f : 0.f) - a2;
        Rt[lane * 33 + c0 + 3] = ((idp && lane == c0 + 3) ? 1.f : 0.f) - a3;
#pragma unroll
        for (int q = 0; q < 4; ++q) {
            int idx = tid + 256 * q;
            int r = idx >> 5, cc = idx & 31;
            Dv[r * 33 + cc] = g_Dinv[rp * 1024 + r * 32 + cc];
        }
        __syncthreads();
        float o0 = 0, o1 = 0, o2 = 0, o3 = 0;
#pragma unroll 8
        for (int k = 0; k < 32; ++k) {
            float dv = Dv[lane * 33 + k];
            const float* rr = &Rt[k * 33 + c0];
            o0 += dv * rr[0]; o1 += dv * rr[1]; o2 += dv * rr[2]; o3 += dv * rr[3];
        }
        Wc[(rbase + lane) * 33 + c0 + 0] = o0;
        Wc[(rbase + lane) * 33 + c0 + 1] = o1;
        Wc[(rbase + lane) * 33 + c0 + 2] = o2;
        Wc[(rbase + lane) * 33 + c0 + 3] = o3;
        __syncthreads();
    }

    for (int idx = tid; idx < 256 * 32; idx += 256) {
        int i = idx >> 5, c = idx & 31;
        g_W[i * C + base + c] = (i >= base) ? Wc[i * 33 + c] : 0.f;
    }
    for (int idx = tid; idx < 256 * 8; idx += 256) {
        int i = idx >> 3, cq = idx & 7;
        float f[4];
#pragma unroll
        for (int e = 0; e < 4; ++e)
            f[e] = (i >= base) ? Wc[i * 33 + cq * 4 + e] : 0.f;
        __nv_bfloat16 h[4], l[4];
#pragma unroll
        for (int e = 0; e < 4; ++e) {
            h[e] = __float2bfloat16_rn(f[e]);
            l[e] = __float2bfloat16_rn(f[e] - __bfloat162float(h[e]));
        }
        int off = i * C + base + cq * 4;
        *(uint2*)(g_Whi + off) = make_uint2(pack2(h[0], h[1]), pack2(h[2], h[3]));
        *(uint2*)(g_Wlo + off) = make_uint2(pack2(l[0], l[1]), pack2(l[2], l[3]));
    }
}

// ---------------- 3c) bias = W @ mean ----------------
__global__ __launch_bounds__(256) void bias_kernel() {
    int i = threadIdx.x;
    float s = 0.f;
#pragma unroll 4
    for (int j = 0; j <= i; ++j) s += g_W[i * C + j] * g_mean[j];
    g_bias[i] = s;
}

// ---------------- 4) whitening: triangular skip, SMSP-balanced (R13-proven) ----------------
// smem: X stages [2][16KB] @0; W stages [3][32KB] @32768.
__global__ __launch_bounds__(512, 1) void whiten_fused(const float* __restrict__ x,
                                                       float* __restrict__ out) {
    extern __shared__ char smem[];
    __shared__ float sbias[C];
    uint32_t sb = smem_u32(smem);

    int tid = threadIdx.x, lane = tid & 31, warp = tid >> 5;
    int wm = warp & 3, wn = warp >> 2;
    int g4 = lane >> 2, t4 = lane & 3;
    int lrow = lane & 15, lpp = lane >> 4;
    size_t m0 = (size_t)blockIdx.x * 128;
    int mylast = 2 * wn + 1;

    if (tid < C) sbias[tid] = g_bias[tid];

    float acc[2][8][4];
#pragma unroll
    for (int a = 0; a < 2; ++a)
#pragma unroll
        for (int b = 0; b < 8; ++b)
#pragma unroll
            for (int r = 0; r < 4; ++r) acc[a][b][r] = 0.f;

    int xrow = tid >> 2, xpp = tid & 3;
    const float* xp = x + (m0 + xrow) * C + xpp * 8;

    auto issueW = [&](int cc, int st) {
        int k0 = cc * 32;
#pragma unroll
        for (int q = 0; q < 4; ++q) {
            int idx = tid + 512 * q;
            int plm = idx >> 10, rem = idx & 1023;
            int n = rem >> 2, sl = (rem >> 1) & 1, pp = rem & 1;
            const __nv_bfloat16* plane = plm ? g_Wlo : g_Whi;
            cp16(sb + 32768u + (uint32_t)st * 32768 + (uint32_t)plm * 16384 +
                     (uint32_t)sl * 8192 + sw16(n, pp),
                 plane + (size_t)n * C + k0 + sl * 16 + pp * 8);
        }
    };

    float4 xv0 = *(const float4*)(xp);
    float4 xv1 = *(const float4*)(xp + 4);
    issueW(0, 0); CP_COMMIT();

    for (int c = 0; c < WH_NCH; ++c) {
        int ps = c & 1;
        int st = c % 3;
        {
            float f[8] = {xv0.x, xv0.y, xv0.z, xv0.w, xv1.x, xv1.y, xv1.z, xv1.w};
            uint4 H, L;
            split8(f, H, L);
            uint32_t off = (uint32_t)ps * 16384 + (uint32_t)(xpp >> 1) * 4096 + sw16(xrow, xpp & 1);
            *(uint4*)(smem + off) = H;
            *(uint4*)(smem + 8192 + off) = L;
        }
        if (c + 1 < WH_NCH) {
            xv0 = *(const float4*)(xp + (c + 1) * 32);
            xv1 = *(const float4*)(xp + (c + 1) * 32 + 4);
            issueW(c + 1, (c + 1) % 3); CP_COMMIT(); CP_WAIT1();
        } else CP_WAIT0();
        __syncthreads();

        if (c <= mylast) {
#pragma unroll
            for (int ks = 0; ks < 2; ++ks) {
                uint32_t XH = sb + (uint32_t)ps * 16384 + (uint32_t)ks * 4096;
                uint32_t XL = XH + 8192;
                uint32_t WHb = sb + 32768u + (uint32_t)st * 32768 + (uint32_t)ks * 8192;
                uint32_t WLb = WHb + 16384;
                uint32_t bh[8][2], bl[8][2];
#pragma unroll
                for (int np = 0; np < 4; ++np) {
                    int nr = wn * 64 + np * 16 + lrow;
                    ldsm4(bh[np * 2][0], bh[np * 2 + 1][0], bh[np * 2][1], bh[np * 2 + 1][1],
                          WHb + sw16(nr, lpp));
                    ldsm4(bl[np * 2][0], bl[np * 2 + 1][0], bl[np * 2][1], bl[np * 2 + 1][1],
                          WLb + sw16(nr, lpp));
                }
#pragma unroll
                for (int mf = 0; mf < 2; ++mf) {
                    int mr = wm * 32 + mf * 16 + lrow;
                    uint32_t ah[4], al[4];
                    ldsm4(ah[0], ah[1], ah[2], ah[3], XH + sw16(mr, lpp));
                    ldsm4(al[0], al[1], al[2], al[3], XL + sw16(mr, lpp));
#pragma unroll
                    for (int nf = 0; nf < 8; ++nf) {
                        mma_bf16(acc[mf][nf], ah, bh[nf]);
                        mma_bf16(acc[mf][nf], ah, bl[nf]);
                        mma_bf16(acc[mf][nf], al, bh[nf]);
                    }
                }
            }
        }
    }

#pragma unroll
    for (int mf = 0; mf < 2; ++mf)
#pragma unroll
        for (int nf = 0; nf < 8; ++nf) {
            int r = wm * 32 + mf * 16 + g4;
            int cc = wn * 64 + nf * 8 + t4 * 2;
            float b0 = sbias[cc], b1 = sbias[cc + 1];
            *(float2*)&out[(m0 + r) * C + cc]     = make_float2(acc[mf][nf][0] - b0, acc[mf][nf][1] - b1);
            *(float2*)&out[(m0 + r + 8) * C + cc] = make_float2(acc[mf][nf][2] - b0, acc[mf][nf][3] - b1);
        }
}

// ---------------- launch ----------------
extern "C" void kernel_launch(void* const* d_in, const int* in_sizes, int n_in,
                              void* d_out, int out_size) {
    const float* x = (const float*)d_in[0];
    float* out = (float*)d_out;
    int rows = in_sizes[0] / C;          // 131072

    static const int syrk_smem = 98304;
    cudaFuncSetAttribute(syrk_fused, cudaFuncAttributeMaxDynamicSharedMemorySize, syrk_smem);
    syrk_fused<<<NBT, 256, syrk_smem>>>(x);

    reduceG2_kernel<<<dim3(3, 64), 256>>>();

    static const int chol_smem = (C * (C + 1) / 2) * (int)sizeof(float);  // 131584
    cudaFuncSetAttribute(chol_factor, cudaFuncAttributeMaxDynamicSharedMemorySize, chol_smem);
    chol_factor<<<1, 256, chol_smem>>>(rows);

    static const int trsm_smem = (C * (C + 1) / 2 + C * 33) * (int)sizeof(float);  // 165376
    cudaFuncSetAttribute(trsm_inv, cudaFuncAttributeMaxDynamicSharedMemorySize, trsm_smem);
    trsm_inv<<<8, 256, trsm_smem>>>();

    bias_kernel<<<1, 256>>>();

    static const int wh_smem = 131072;
    cudaFuncSetAttribute(whiten_fused, cudaFuncAttributeMaxDynamicSharedMemorySize, wh_smem);
    whiten_fused<<<rows / 128, 512, wh_smem>>>(x, out);
}

// round 17
// speedup vs baseline: 1.1004x; 1.0095x over previous
#include <cuda_runtime.h>
#include <cuda_bf16.h>
#include <math.h>
#include <stdint.h>

#define C 256
#define ROWS 131072
#define EPS 0.001f
#define TOTCH 4096           // total K-chunks of 32 rows
#define NBH 88               // split-K blocks per half pair (p=0,2)
#define NBF 120              // split-K blocks for full pair (p=1)
#define NBT (NBH + NBF + NBH)   // 296 = one full wave at 2 blocks/SM
#define WH_NCH 8             // whiten k-chunks (256/32)

// ---------------- scratch ----------------
__device__ float g_psum[NBF * C];
__device__ float g_pG2[(size_t)NBT * 128 * 128];
__device__ float g_G[C * C];
__device__ float g_Lp[C * (C + 1) / 2];
__device__ float g_mean[C];
__device__ float g_Dinv[8 * 32 * 32];
__device__ float g_W[C * C];
__device__ float g_bias[C];
__device__ __nv_bfloat16 g_Whi[C * C];
__device__ __nv_bfloat16 g_Wlo[C * C];

__constant__ int c2_pi[3] = {0, 0, 1};
__constant__ int c2_pj[3] = {0, 1, 1};
__constant__ int c_off[3] = {0, NBH, NBH + NBF};
__constant__ int c_cnt[3] = {NBH, NBF, NBH};

// ---------------- helpers ----------------
__device__ __forceinline__ uint32_t smem_u32(const void* p) {
    uint32_t a;
    asm("{ .reg .u64 t; cvta.to.shared.u64 t, %1; cvt.u32.u64 %0, t; }" : "=r"(a) : "l"(p));
    return a;
}
__device__ __forceinline__ void cp16(uint32_t dst, const void* src) {
    asm volatile("cp.async.cg.shared.global [%0], [%1], 16;" :: "r"(dst), "l"(src));
}
#define CP_COMMIT() asm volatile("cp.async.commit_group;" ::: "memory")
#define CP_WAIT1()  asm volatile("cp.async.wait_group 1;" ::: "memory")
#define CP_WAIT0()  asm volatile("cp.async.wait_group 0;" ::: "memory")

__device__ __forceinline__ void mma_bf16(float* d, const uint32_t* a, const uint32_t* b) {
    asm volatile(
        "mma.sync.aligned.m16n8k16.row.col.f32.bf16.bf16.f32 "
        "{%0,%1,%2,%3}, {%4,%5,%6,%7}, {%8,%9}, {%0,%1,%2,%3};\n"
        : "+f"(d[0]), "+f"(d[1]), "+f"(d[2]), "+f"(d[3])
        : "r"(a[0]), "r"(a[1]), "r"(a[2]), "r"(a[3]), "r"(b[0]), "r"(b[1]));
}
__device__ __forceinline__ void ldsm4(uint32_t& d0, uint32_t& d1, uint32_t& d2, uint32_t& d3,
                                      uint32_t a) {
    asm volatile("ldmatrix.sync.aligned.m8n8.x4.shared.b16 {%0,%1,%2,%3}, [%4];"
                 : "=r"(d0), "=r"(d1), "=r"(d2), "=r"(d3) : "r"(a));
}
__device__ __forceinline__ uint32_t pack2(__nv_bfloat16 lo, __nv_bfloat16 hi) {
    return (uint32_t)__bfloat16_as_ushort(lo) | ((uint32_t)__bfloat16_as_ushort(hi) << 16);
}
__device__ __forceinline__ uint32_t sw16(int row, int pp) {
    return ((uint32_t)(((row << 1) | pp) ^ ((row >> 2) & 1))) << 4;
}
// fast hi/lo split: packed bf16x2 converts (rn both; bit-identical to scalar rn path)
__device__ __forceinline__ void split8(const float* f, uint4& H, uint4& L) {
    uint32_t h[4], l[4];
#pragma unroll
    for (int e = 0; e < 4; ++e) {
        asm("cvt.rn.bf16x2.f32 %0, %1, %2;" : "=r"(h[e]) : "f"(f[2 * e + 1]), "f"(f[2 * e]));
        float h0 = __uint_as_float(h[e] << 16);
        float h1 = __uint_as_float(h[e] & 0xFFFF0000u);
        float l0 = f[2 * e] - h0;
        float l1 = f[2 * e + 1] - h1;
        asm("cvt.rn.bf16x2.f32 %0, %1, %2;" : "=r"(l[e]) : "f"(l1), "f"(l0));
    }
    H = make_uint4(h[0], h[1], h[2], h[3]);
    L = make_uint4(l[0], l[1], l[2], l[3]);
}

// ---------------- 1) SYRK fused: one-wave, work-balanced split-K (R14-proven) ----------------
// smem bytes: fp32 stages [2][32KB] @0; planes @65536: AH,AL,BH,BL 8KB each.
__global__ __launch_bounds__(256, 2) void syrk_fused(const float* __restrict__ x) {
    extern __shared__ char smem[];
    uint32_t sb = smem_u32(smem);
    uint32_t pl = sb + 65536;
    const float* sf = (const float*)smem;

    int tid = threadIdx.x, lane = tid & 31, warp = tid >> 5;
    int wm = warp >> 2, wn = warp & 3;
    int g4 = lane >> 2, t4 = lane & 3;
    int lrow = lane & 15, lpp = lane >> 4;

    int bid = blockIdx.x;
    int p, idx;
    if (bid < NBH)            { p = 0; idx = bid; }
    else if (bid < NBH + NBF) { p = 1; idx = bid - NBH; }
    else                      { p = 2; idx = bid - NBH - NBF; }
    int nb = (p == 1) ? NBF : NBH;
    int cs = (int)(((long long)idx * TOTCH) / nb);
    int ce = (int)(((long long)(idx + 1) * TOTCH) / nb);
    int nch = ce - cs;

    int ti = c2_pi[p];
    bool full = (p == 1);
    size_t k0base = (size_t)cs * 32;
    uint32_t bBase = pl + (full ? 16384u : 0u);

    float acc[4][4][4];
#pragma unroll
    for (int a = 0; a < 4; ++a)
#pragma unroll
        for (int b = 0; b < 4; ++b)
#pragma unroll
            for (int r = 0; r < 4; ++r) acc[a][b][r] = 0.f;
    float csum = 0.f;

    auto issue = [&](int cc, int s) {
        size_t k0 = k0base + (size_t)cc * 32;
        if (full) {
#pragma unroll
            for (int q = 0; q < 8; ++q) {
                int i2 = tid + 256 * q;
                int row = i2 >> 6, pc = i2 & 63;
                cp16(sb + (uint32_t)s * 32768 + (uint32_t)row * 1024 + (uint32_t)pc * 16,
                     x + (k0 + row) * C + pc * 4);
            }
        } else {
#pragma unroll
            for (int q = 0; q < 4; ++q) {
                int i2 = tid + 256 * q;
                int row = i2 >> 5, pc = i2 & 31;
                cp16(sb + (uint32_t)s * 32768 + (uint32_t)row * 512 + (uint32_t)pc * 16,
                     x + (k0 + row) * C + ti * 128 + pc * 4);
            }
        }
    };

    issue(0, 0); CP_COMMIT();
    for (int c = 0; c < nch; ++c) {
        int s = c & 1;
        if (c + 1 < nch) { issue(c + 1, s ^ 1); CP_COMMIT(); CP_WAIT1(); }
        else CP_WAIT0();
        __syncthreads();

        if (full) {
            int ch = tid;
            uint32_t stg = (uint32_t)s * 8192;
            uint32_t boff = 65536u + (uint32_t)(ch >> 7) * 16384;
            int chl = ch & 127;
#pragma unroll
            for (int kp = 0; kp < 4; ++kp) {
                float f[8];
#pragma unroll
                for (int e = 0; e < 8; ++e) {
                    f[e] = sf[stg + (uint32_t)(kp * 8 + e) * 256 + ch];
                    csum += f[e];
                }
                uint4 H, L;
                split8(f, H, L);
                uint32_t off = (uint32_t)(kp >> 1) * 4096 + sw16(chl, kp & 1);
                *(uint4*)(smem + boff + off) = H;
                *(uint4*)(smem + boff + 8192 + off) = L;
            }
        } else {
            int ch = tid & 127, kb = tid >> 7;
            uint32_t stg = (uint32_t)s * 8192;
#pragma unroll
            for (int q = 0; q < 2; ++q) {
                int kp = kb * 2 + q;
                float f[8];
#pragma unroll
                for (int e = 0; e < 8; ++e)
                    f[e] = sf[stg + (uint32_t)(kp * 8 + e) * 128 + ch];
                uint4 H, L;
                split8(f, H, L);
                uint32_t off = (uint32_t)(kp >> 1) * 4096 + sw16(ch, kp & 1);
                *(uint4*)(smem + 65536 + off) = H;
                *(uint4*)(smem + 65536 + 8192 + off) = L;
            }
        }
        __syncthreads();

#pragma unroll
        for (int ks = 0; ks < 2; ++ks) {
            uint32_t AH = pl + (uint32_t)ks * 4096;
            uint32_t AL = AH + 8192;
            uint32_t BH = bBase + (uint32_t)ks * 4096;
            uint32_t BL = BH + 8192;
            uint32_t bh[4][2], bl[4][2];
#pragma unroll
            for (int np = 0; np < 2; ++np) {
                int nr = wn * 32 + np * 16 + lrow;
                ldsm4(bh[np * 2][0], bh[np * 2 + 1][0], bh[np * 2][1], bh[np * 2 + 1][1],
                      BH + sw16(nr, lpp));
                ldsm4(bl[np * 2][0], bl[np * 2 + 1][0], bl[np * 2][1], bl[np * 2 + 1][1],
                      BL + sw16(nr, lpp));
            }
#pragma unroll
            for (int mf = 0; mf < 4; ++mf) {
                int mr = wm * 64 + mf * 16 + lrow;
                uint32_t ah[4], al[4];
                ldsm4(ah[0], ah[1], ah[2], ah[3], AH + sw16(mr, lpp));
                ldsm4(al[0], al[1], al[2], al[3], AL + sw16(mr, lpp));
#pragma unroll
                for (int nf = 0; nf < 4; ++nf) {
                    mma_bf16(acc[mf][nf], ah, bh[nf]);
                    mma_bf16(acc[mf][nf], ah, bl[nf]);
                    mma_bf16(acc[mf][nf], al, bh[nf]);
                }
            }
        }
    }

    if (full) g_psum[idx * C + tid] = csum;

    float* dst = g_pG2 + (size_t)bid * 16384;
#pragma unroll
    for (int mf = 0; mf < 4; ++mf)
#pragma unroll
        for (int nf = 0; nf < 4; ++nf) {
            int r = wm * 64 + mf * 16 + g4;
            int cc = wn * 32 + nf * 8 + t4 * 2;
            dst[r * 128 + cc]           = acc[mf][nf][0];
            dst[r * 128 + cc + 1]       = acc[mf][nf][1];
            dst[(r + 8) * 128 + cc]     = acc[mf][nf][2];
            dst[(r + 8) * 128 + cc + 1] = acc[mf][nf][3];
        }
}

// ---------------- 2) deterministic reduction: 4 independent accumulator chains ----------------
__global__ __launch_bounds__(256) void reduceG2_kernel() {
    int p = blockIdx.x;
    int e = blockIdx.y * 256 + threadIdx.x;
    int cnt = c_cnt[p];
    const float* src = g_pG2 + (size_t)c_off[p] * 16384 + e;
    float s0 = 0.f, s1 = 0.f, s2 = 0.f, s3 = 0.f;
    int c = 0;
    for (; c + 4 <= cnt; c += 4) {
        s0 += src[(size_t)(c + 0) * 16384];
        s1 += src[(size_t)(c + 1) * 16384];
        s2 += src[(size_t)(c + 2) * 16384];
        s3 += src[(size_t)(c + 3) * 16384];
    }
    for (; c < cnt; ++c) s0 += src[(size_t)c * 16384];
    float s = (s0 + s1) + (s2 + s3);
    int a = e >> 7, b = e & 127;
    int gi = c2_pi[p] * 128 + a, gj = c2_pj[p] * 128 + b;
    g_G[gi * C + gj] = s;
    g_G[gj * C + gi] = s;
}

// ---------------- 3a) mean + blocked Cholesky factor -> g_Lp, g_mean, g_Dinv ----------------
extern "C" __global__ __launch_bounds__(256) void chol_factor(int rows) {
    extern __shared__ float Lp[];
    __shared__ float m[C];
    __shared__ float scrD[32 * 33];
    __shared__ float sdinv[32];
    int tid = threadIdx.x, lane = tid & 31, warp = tid >> 5;

    {
        float s = 0.f;
#pragma unroll 8
        for (int b = 0; b < NBF; ++b) s += g_psum[b * C + tid];
        m[tid] = s / (float)rows;
    }
    __syncthreads();

    const int TOT = C * (C + 1) / 2;
    float scale = (1.f - EPS) / (float)(rows - 1);
    for (int idx = tid; idx < TOT; idx += 256) {
        int i = (int)((sqrtf(8.f * (float)idx + 1.f) - 1.f) * 0.5f);
        while ((i + 1) * (i + 2) / 2 <= idx) ++i;
        while (i * (i + 1) / 2 > idx) --i;
        int j = idx - i * (i + 1) / 2;
        float v = (g_G[i * C + j] - (float)rows * m[i] * m[j]) * scale;
        if (i == j) v += EPS;
        Lp[idx] = v;
    }
    __syncthreads();

    for (int pb = 0; pb < 8; ++pb) {
        int base = pb * 32;
        for (int idx = tid; idx < 1024; idx += 256) {
            int i = idx >> 5, j = idx & 31;
            int gi = base + i;
            scrD[i * 33 + j] = (j <= i) ? Lp[gi * (gi + 1) / 2 + base + j] : 0.f;
        }
        __syncthreads();
        if (warp == 0) {
            for (int k = 0; k < 32; ++k) {
                if (lane == 0) scrD[k * 33 + k] = sqrtf(scrD[k * 33 + k]);
                __syncwarp();
                float inv = 1.f / scrD[k * 33 + k];
                if (lane > k) scrD[lane * 33 + k] *= inv;
                __syncwarp();
                if (lane > k) {
                    float lik = scrD[lane * 33 + k];
                    for (int j = k + 1; j <= lane; ++j)
                        scrD[lane * 33 + j] -= lik * scrD[j * 33 + k];
                }
                __syncwarp();
            }
        }
        __syncthreads();
        if (tid < 32) sdinv[tid] = 1.f / scrD[tid * 33 + tid];
        for (int idx = tid; idx < 1024; idx += 256) {
            int i = idx >> 5, j = idx & 31;
            if (j <= i) {
                int gi = base + i;
                Lp[gi * (gi + 1) / 2 + base + j] = scrD[i * 33 + j];
            }
        }
        __syncthreads();
        int R = 256 - base - 32;
        if (tid < R) {
            int gi = base + 32 + tid;
            int ro = gi * (gi + 1) / 2 + base;
            float r[32];
#pragma unroll
            for (int t = 0; t < 32; ++t) r[t] = Lp[ro + t];
#pragma unroll
            for (int k = 0; k < 32; ++k) {
                float s = r[k];
                for (int t = 0; t < k; ++t) s -= r[t] * scrD[k * 33 + t];
                r[k] = s * sdinv[k];
            }
#pragma unroll
            for (int t = 0; t < 32; ++t) Lp[ro + t] = r[t];
        }
        __syncthreads();
        if (R > 0) {
            int w = warp;
            for (int rt = 0; rt * 128 < R; ++rt) {
                int gbase = base + 32 + rt * 128;
                int tmax = min(255, gbase + 127);
                int gi[4]; bool act[4];
                float pi[4][32];
#pragma unroll
                for (int q = 0; q < 4; ++q) {
                    gi[q] = gbase + q * 32 + lane;
                    act[q] = gi[q] < 256;
                    if (act[q]) {
                        int ro = gi[q] * (gi[q] + 1) / 2 + base;
#pragma unroll
                        for (int t = 0; t < 32; ++t) pi[q][t] = Lp[ro + t];
                    }
                }
                for (int jt = base + 32; jt <= tmax; jt += 32) {
                    int j0 = jt + w * 4;
                    if (j0 > tmax) continue;
                    int rj0 = j0 * (j0 + 1) / 2 + base;
                    int rj1 = (j0 + 1) * (j0 + 2) / 2 + base;
                    int rj2 = (j0 + 2) * (j0 + 3) / 2 + base;
                    int rj3 = (j0 + 3) * (j0 + 4) / 2 + base;
                    float a[4][4];
#pragma unroll
                    for (int q = 0; q < 4; ++q)
#pragma unroll
                        for (int e = 0; e < 4; ++e) a[q][e] = 0.f;
#pragma unroll
                    for (int k = 0; k < 32; ++k) {
                        float pj0 = Lp[rj0 + k];
                        float pj1 = Lp[rj1 + k];
                        float pj2 = Lp[rj2 + k];
                        float pj3 = Lp[rj3 + k];
#pragma unroll
                        for (int q = 0; q < 4; ++q) {
                            float pv = pi[q][k];
                            a[q][0] += pv * pj0;
                            a[q][1] += pv * pj1;
                            a[q][2] += pv * pj2;
                            a[q][3] += pv * pj3;
                        }
                    }
#pragma unroll
                    for (int q = 0; q < 4; ++q) {
                        if (!act[q]) continue;
                        int ro = gi[q] * (gi[q] + 1) / 2;
#pragma unroll
                        for (int e = 0; e < 4; ++e) {
                            int j = j0 + e;
                            if (j <= gi[q]) Lp[ro + j] -= a[q][e];
                        }
                    }
                }
            }
        }
        __syncthreads();
    }

    {
        int b = tid >> 5, j = tid & 31, rb = b * 32;
        float w[32];
#pragma unroll
        for (int i = 0; i < 32; ++i) {
            float s = (i == j) ? 1.f : 0.f;
            const float* lrow = &Lp[(rb + i) * (rb + i + 1) / 2 + rb];
#pragma unroll
            for (int k = 0; k < 32; ++k)
                if (k < i) s -= lrow[k] * w[k];
            w[i] = (i >= j) ? s / lrow[i] : 0.f;
        }
#pragma unroll
        for (int i = 0; i < 32; ++i) g_Dinv[b * 1024 + i * 32 + j] = w[i];
    }

    for (int idx = tid; idx < TOT; idx += 256) g_Lp[idx] = Lp[idx];
    if (tid < C) g_mean[tid] = m[tid];
}

// ---------------- 3b) panel TRSM via Dinv GEMMs ----------------
__global__ __launch_bounds__(256) void trsm_inv() {
    extern __shared__ float sh[];
    float* Lpack = sh;
    float* Wc = sh + 32896;
    __shared__ float Rt[32 * 33];
    __shared__ float Dv[32 * 33];
    int tid = threadIdx.x, lane = tid & 31, w = tid >> 5;
    int base = blockIdx.x * 32;
    int pb0 = blockIdx.x;
    int c0 = w * 4;

    for (int idx = tid; idx < C * (C + 1) / 2; idx += 256) Lpack[idx] = g_Lp[idx];
    __syncthreads();

    for (int rp = pb0; rp < 8; ++rp) {
        int rbase = rp * 32;
        float a0 = 0, a1 = 0, a2 = 0, a3 = 0;
        for (int pp = pb0; pp < rp; ++pp) {
            int kb = pp * 32;
            int ro = (rbase + lane) * (rbase + lane + 1) / 2 + kb;
#pragma unroll 8
            for (int k = 0; k < 32; ++k) {
                float lv = Lpack[ro + k];
                const float* wr = &Wc[(kb + k) * 33 + c0];
                a0 += lv * wr[0]; a1 += lv * wr[1]; a2 += lv * wr[2]; a3 += lv * wr[3];
            }
        }
        bool idp = (rp == pb0);
        Rt[lane * 33 + c0 + 0] = ((idp && lane == c0 + 0) ? 1.f : 0.f) - a0;
        Rt[lane * 33 + c0 + 1] = ((idp && lane == c0 + 1) ? 1.f : 0.f) - a1;
        Rt[lane * 33 + c0 + 2] = ((idp && lane == c0 + 2) ? 1.f : 0.f) - a2;
        Rt[lane * 33 + c0 + 3] = ((idp && lane == c0 + 3) ? 1.f : 0.f) - a3;
#pragma unroll
        for (int q = 0; q < 4; ++q) {
            int idx = tid + 256 * q;
            int r = idx >> 5, cc = idx & 31;
            Dv[r * 33 + cc] = g_Dinv[rp * 1024 + r * 32 + cc];
        }
        __syncthreads();
        float o0 = 0, o1 = 0, o2 = 0, o3 = 0;
#pragma unroll 8
        for (int k = 0; k < 32; ++k) {
            float dv = Dv[lane * 33 + k];
            const float* rr = &Rt[k * 33 + c0];
            o0 += dv * rr[0]; o1 += dv * rr[1]; o2 += dv * rr[2]; o3 += dv * rr[3];
        }
        Wc[(rbase + lane) * 33 + c0 + 0] = o0;
        Wc[(rbase + lane) * 33 + c0 + 1] = o1;
        Wc[(rbase + lane) * 33 + c0 + 2] = o2;
        Wc[(rbase + lane) * 33 + c0 + 3] = o3;
        __syncthreads();
    }

    for (int idx = tid; idx < 256 * 32; idx += 256) {
        int i = idx >> 5, c = idx & 31;
        g_W[i * C + base + c] = (i >= base) ? Wc[i * 33 + c] : 0.f;
    }
    for (int idx = tid; idx < 256 * 8; idx += 256) {
        int i = idx >> 3, cq = idx & 7;
        float f[4];
#pragma unroll
        for (int e = 0; e < 4; ++e)
            f[e] = (i >= base) ? Wc[i * 33 + cq * 4 + e] : 0.f;
        __nv_bfloat16 h[4], l[4];
#pragma unroll
        for (int e = 0; e < 4; ++e) {
            h[e] = __float2bfloat16_rn(f[e]);
            l[e] = __float2bfloat16_rn(f[e] - __bfloat162float(h[e]));
        }
        int off = i * C + base + cq * 4;
        *(uint2*)(g_Whi + off) = make_uint2(pack2(h[0], h[1]), pack2(h[2], h[3]));
        *(uint2*)(g_Wlo + off) = make_uint2(pack2(l[0], l[1]), pack2(l[2], l[3]));
    }
}

// ---------------- 3c) bias = W @ mean ----------------
__global__ __launch_bounds__(256) void bias_kernel() {
    int i = threadIdx.x;
    float s = 0.f;
#pragma unroll 4
    for (int j = 0; j <= i; ++j) s += g_W[i * C + j] * g_mean[j];
    g_bias[i] = s;
}

// ---------------- 4) whitening: triangular skip, SMSP-balanced (R13-proven) ----------------
// smem: X stages [2][16KB] @0; W stages [3][32KB] @32768.
__global__ __launch_bounds__(512, 1) void whiten_fused(const float* __restrict__ x,
                                                       float* __restrict__ out) {
    extern __shared__ char smem[];
    __shared__ float sbias[C];
    uint32_t sb = smem_u32(smem);

    int tid = threadIdx.x, lane = tid & 31, warp = tid >> 5;
    int wm = warp & 3, wn = warp >> 2;
    int g4 = lane >> 2, t4 = lane & 3;
    int lrow = lane & 15, lpp = lane >> 4;
    size_t m0 = (size_t)blockIdx.x * 128;
    int mylast = 2 * wn + 1;

    if (tid < C) sbias[tid] = g_bias[tid];

    float acc[2][8][4];
#pragma unroll
    for (int a = 0; a < 2; ++a)
#pragma unroll
        for (int b = 0; b < 8; ++b)
#pragma unroll
            for (int r = 0; r < 4; ++r) acc[a][b][r] = 0.f;

    int xrow = tid >> 2, xpp = tid & 3;
    const float* xp = x + (m0 + xrow) * C + xpp * 8;

    auto issueW = [&](int cc, int st) {
        int k0 = cc * 32;
#pragma unroll
        for (int q = 0; q < 4; ++q) {
            int idx = tid + 512 * q;
            int plm = idx >> 10, rem = idx & 1023;
            int n = rem >> 2, sl = (rem >> 1) & 1, pp = rem & 1;
            const __nv_bfloat16* plane = plm ? g_Wlo : g_Whi;
            cp16(sb + 32768u + (uint32_t)st * 32768 + (uint32_t)plm * 16384 +
                     (uint32_t)sl * 8192 + sw16(n, pp),
                 plane + (size_t)n * C + k0 + sl * 16 + pp * 8);
        }
    };

    float4 xv0 = *(const float4*)(xp);
    float4 xv1 = *(const float4*)(xp + 4);
    issueW(0, 0); CP_COMMIT();

    for (int c = 0; c < WH_NCH; ++c) {
        int ps = c & 1;
        int st = c % 3;
        {
            float f[8] = {xv0.x, xv0.y, xv0.z, xv0.w, xv1.x, xv1.y, xv1.z, xv1.w};
            uint4 H, L;
            split8(f, H, L);
            uint32_t off = (uint32_t)ps * 16384 + (uint32_t)(xpp >> 1) * 4096 + sw16(xrow, xpp & 1);
            *(uint4*)(smem + off) = H;
            *(uint4*)(smem + 8192 + off) = L;
        }
        if (c + 1 < WH_NCH) {
            xv0 = *(const float4*)(xp + (c + 1) * 32);
            xv1 = *(const float4*)(xp + (c + 1) * 32 + 4);
            issueW(c + 1, (c + 1) % 3); CP_COMMIT(); CP_WAIT1();
        } else CP_WAIT0();
        __syncthreads();

        if (c <= mylast) {
#pragma unroll
            for (int ks = 0; ks < 2; ++ks) {
                uint32_t XH = sb + (uint32_t)ps * 16384 + (uint32_t)ks * 4096;
                uint32_t XL = XH + 8192;
                uint32_t WHb = sb + 32768u + (uint32_t)st * 32768 + (uint32_t)ks * 8192;
                uint32_t WLb = WHb + 16384;
                uint32_t bh[8][2], bl[8][2];
#pragma unroll
                for (int np = 0; np < 4; ++np) {
                    int nr = wn * 64 + np * 16 + lrow;
                    ldsm4(bh[np * 2][0], bh[np * 2 + 1][0], bh[np * 2][1], bh[np * 2 + 1][1],
                          WHb + sw16(nr, lpp));
                    ldsm4(bl[np * 2][0], bl[np * 2 + 1][0], bl[np * 2][1], bl[np * 2 + 1][1],
                          WLb + sw16(nr, lpp));
                }
#pragma unroll
                for (int mf = 0; mf < 2; ++mf) {
                    int mr = wm * 32 + mf * 16 + lrow;
                    uint32_t ah[4], al[4];
                    ldsm4(ah[0], ah[1], ah[2], ah[3], XH + sw16(mr, lpp));
                    ldsm4(al[0], al[1], al[2], al[3], XL + sw16(mr, lpp));
#pragma unroll
                    for (int nf = 0; nf < 8; ++nf) {
                        mma_bf16(acc[mf][nf], ah, bh[nf]);
                        mma_bf16(acc[mf][nf], ah, bl[nf]);
                        mma_bf16(acc[mf][nf], al, bh[nf]);
                    }
                }
            }
        }
    }

#pragma unroll
    for (int mf = 0; mf < 2; ++mf)
#pragma unroll
        for (int nf = 0; nf < 8; ++nf) {
            int r = wm * 32 + mf * 16 + g4;
            int cc = wn * 64 + nf * 8 + t4 * 2;
            float b0 = sbias[cc], b1 = sbias[cc + 1];
            *(float2*)&out[(m0 + r) * C + cc]     = make_float2(acc[mf][nf][0] - b0, acc[mf][nf][1] - b1);
            *(float2*)&out[(m0 + r + 8) * C + cc] = make_float2(acc[mf][nf][2] - b0, acc[mf][nf][3] - b1);
        }
}

// ---------------- launch ----------------
extern "C" void kernel_launch(void* const* d_in, const int* in_sizes, int n_in,
                              void* d_out, int out_size) {
    const float* x = (const float*)d_in[0];
    float* out = (float*)d_out;
    int rows = in_sizes[0] / C;          // 131072

    static const int syrk_smem = 98304;
    cudaFuncSetAttribute(syrk_fused, cudaFuncAttributeMaxDynamicSharedMemorySize, syrk_smem);
    syrk_fused<<<NBT, 256, syrk_smem>>>(x);

    reduceG2_kernel<<<dim3(3, 64), 256>>>();

    static const int chol_smem = (C * (C + 1) / 2) * (int)sizeof(float);  // 131584
    cudaFuncSetAttribute(chol_factor, cudaFuncAttributeMaxDynamicSharedMemorySize, chol_smem);
    chol_factor<<<1, 256, chol_smem>>>(rows);

    static const int trsm_smem = (C * (C + 1) / 2 + C * 33) * (int)sizeof(float);  // 165376
    cudaFuncSetAttribute(trsm_inv, cudaFuncAttributeMaxDynamicSharedMemorySize, trsm_smem);
    trsm_inv<<<8, 256, trsm_smem>>>();

    bias_kernel<<<1, 256>>>();

    static const int wh_smem = 131072;
    cudaFuncSetAttribute(whiten_fused, cudaFuncAttributeMaxDynamicSharedMemorySize, wh_smem);
    whiten_fused<<<rows / 128, 512, wh_smem>>>(x, out);
}